// round 12
// baseline (speedup 1.0000x reference)
#include <cuda_runtime.h>
#include <stdint.h>

// Problem constants
#define NB       64
#define NH       512
#define NUM_MASK 3072          // masked patches per image

// ---------------------------------------------------------------------------
// Single fused kernel — R4 memory pattern, 768-thread blocks covering TWO
// patch rows CONCURRENTLY (thread halves own disjoint bands; warp-level
// access pattern is byte-identical to the proven R4 config, and SM warp
// residency is identical: 2 blocks x 24 warps = 4 x 12).
//
// Grid (32 patch-row pairs, 64 images); block = 768 threads.
//
// Prologue: build the 128-patch masked bitmap for the pair of patch rows:
// each thread reads 4 of the image's 3072 indices (coalesced; 12 KB slice
// shared by 32 blocks -> L2 resident), range-tests, atomicOr into 4 smem
// words. Half the per-byte prologue cost of the 384-thread version.
//
// Main: thread t -> band sub = t/384 (patch row pr = 2*prp + sub), float4
// column c = t%384. Each thread: keep -> 8x LDG.128 front-batched (MLP=8)
// + 8x STG.128; drop -> 8x STG.128 of zeros, image never read (saves 75%
// of read traffic). Row stride = 384 float4 = 6144 B; fully coalesced.
__global__ void __launch_bounds__(768)
random_mask_kernel(const float4* __restrict__ img,
                   const int*    __restrict__ mask_indices,
                   float4*       __restrict__ out) {
    const int prp = blockIdx.x;           // patch-row pair [0, 32)
    const int b   = blockIdx.y;           // image          [0, 64)
    const int t   = threadIdx.x;          // [0, 768)

    // ---- build 128-bit masked-bitmap for this (image, patch-row pair) ----
    __shared__ uint32_t masked_bits[4];
    if (t < 4) masked_bits[t] = 0;
    __syncthreads();

    const int* mi = mask_indices + b * NUM_MASK;
    const int lo = prp << 7;              // first patch id of this pair
#pragma unroll
    for (int j = 0; j < 4; j++) {
        int idx = mi[t + j * 768];        // coalesced, L2-resident
        unsigned d = (unsigned)(idx - lo);
        if (d < 128u) atomicOr(&masked_bits[d >> 5], 1u << (d & 31));
    }
    __syncthreads();

    const int sub = t / 384;              // band within pair: 0 or 1
    const int c   = t - sub * 384;        // float4 col [0, 384)
    const int p   = (sub << 6) | (c / 6); // patch within 128-bit map
    const bool keep = !((masked_bits[p >> 5] >> (p & 31)) & 1u);

    // ---- stream the 8-row band ----
    const int pr = (prp << 1) | sub;      // global patch row [0, 64)
    const long base = ((long)(b * NH + (pr << 3)) * 384) + c;
    const float4* ip = img + base;
    float4*       op = out + base;

    if (keep) {
        float4 v[8];
#pragma unroll
        for (int r = 0; r < 8; r++) v[r] = __ldcs(ip + r * 384);
#pragma unroll
        for (int r = 0; r < 8; r++) __stcs(op + r * 384, v[r]);
    } else {
        const float4 z = make_float4(0.f, 0.f, 0.f, 0.f);
#pragma unroll
        for (int r = 0; r < 8; r++) __stcs(op + r * 384, z);
    }
}

// ---------------------------------------------------------------------------
extern "C" void kernel_launch(void* const* d_in, const int* in_sizes, int n_in,
                              void* d_out, int out_size) {
    const float4* img = (const float4*)d_in[0];       // images [64,512,512,3] f32
    const int* mask_indices = (const int*)d_in[1];    // [64, 3072] i32
    float4* out = (float4*)d_out;

    dim3 grid(32, NB);                    // (patch-row pairs, images)
    random_mask_kernel<<<grid, 768>>>(img, mask_indices, out);
}

// round 13
// speedup vs baseline: 1.0336x; 1.0336x over previous
#include <cuda_runtime.h>
#include <stdint.h>

// Problem constants
#define NB       64
#define NH       512
#define NW       512
#define NC       3
#define NUM_MASK 3072          // masked patches per image

// ---------------------------------------------------------------------------
// FINAL kernel (converged optimum — R4 configuration, best measured total
// 47.6 us; kernel ~43.4 us, DRAM ~68% @ ~5.8 TB/s effective on 252 MB).
//
// Grid (NPH=64 patch-rows, NB=64 images); block = 384 threads.
//
// Prologue: build this block's 64-patch keep bitmap directly from
// mask_indices (no intermediate global mask, no builder kernel):
//   - each thread reads 8 indices of this image's 3072 (coalesced; the
//     12 KB slice is shared by 64 blocks -> L2 resident)
//   - range-test against this patch-row, atomicOr into 2 shared words.
//
// Main: a patch spans 8 consecutive rows sharing one mask bit. Each thread
// owns one float4 column across the 8 rows of its patch band:
//   - keep: 8x LDG.128 (front-batched -> MLP=8) + 8x STG.128
//   - drop: 8x STG.128 of zeros, image never read (saves 75% read traffic)
// Consecutive threads touch consecutive float4s within a row -> fully
// coalesced. Row stride = 384 float4 = 6144 B.
//
// Tuning history (single-axis probes off this base, ALL regressed/tied):
// R5 occupancy up (regs 40->30, chunked loads)   -> 44.9 us, DRAM 66%
// R6 2 bands sequential per thread               -> 45.0 us, DRAM 66%
// R7 MLP 16 (2 cols/thread, 192 thr)             -> 44.5 us, DRAM 66%
// R8 default store policy (no .cs)               -> 43.6 us (tie)
// R9 persistent 592 blocks                       -> 49.6 us, DRAM 60%
// R10 256-bit v8.f32 ops                         -> 45.3 us, DRAM 64%
// R12 2 bands concurrent (768 thr)               -> 45.6 us, DRAM 65%
// Remaining gap to spec is HBM read/write turnaround on an 80%-write
// stream; no SM-side lever moved it.
__global__ void __launch_bounds__(384)
random_mask_kernel(const float4* __restrict__ img,
                   const int*    __restrict__ mask_indices,
                   float4*       __restrict__ out) {
    const int pr = blockIdx.x;            // patch row   [0, 64)
    const int b  = blockIdx.y;            // image       [0, 64)
    const int t  = threadIdx.x;           // float4 col  [0, 384)

    // ---- build 64-bit masked-bitmap for this (image, patch-row) ----
    __shared__ uint32_t masked_bits[2];
    if (t < 2) masked_bits[t] = 0;
    __syncthreads();

    const int* mi = mask_indices + b * NUM_MASK;
    const int lo = pr << 6;               // first patch id of this row
#pragma unroll
    for (int j = 0; j < 8; j++) {
        int idx = mi[t + j * 384];        // coalesced, L2-resident
        unsigned d = (unsigned)(idx - lo);
        if (d < 64u) atomicOr(&masked_bits[d >> 5], 1u << (d & 31));
    }
    __syncthreads();

    const int p = t / 6;                  // patch col: 6 float4 per patch
    const bool keep = !((masked_bits[p >> 5] >> (p & 31)) & 1u);

    // ---- stream the 8-row band ----
    const long base = ((long)(b * NH + (pr << 3)) * 384) + t;
    const float4* ip = img + base;
    float4*       op = out + base;

    if (keep) {
        float4 v[8];
#pragma unroll
        for (int r = 0; r < 8; r++) v[r] = __ldcs(ip + r * 384);
#pragma unroll
        for (int r = 0; r < 8; r++) __stcs(op + r * 384, v[r]);
    } else {
        const float4 z = make_float4(0.f, 0.f, 0.f, 0.f);
#pragma unroll
        for (int r = 0; r < 8; r++) __stcs(op + r * 384, z);
    }
}

// ---------------------------------------------------------------------------
extern "C" void kernel_launch(void* const* d_in, const int* in_sizes, int n_in,
                              void* d_out, int out_size) {
    const float4* img = (const float4*)d_in[0];       // images [64,512,512,3] f32
    const int* mask_indices = (const int*)d_in[1];    // [64, 3072] i32
    float4* out = (float4*)d_out;

    dim3 grid(64, NB);                    // (patch-rows, images)
    random_mask_kernel<<<grid, 384>>>(img, mask_indices, out);
}